// round 2
// baseline (speedup 1.0000x reference)
#include <cuda_runtime.h>

// SagPoolBindingNet: B=4096 graphs, N=64 nodes, band adjacency (|i-j|<=2).
// One CTA per graph; band structure exploited so the 64MB adj input is never read.
// Feature rows padded to stride 132 floats (528B, 16B-aligned) to break the
// stride-128 == 0 (mod 32 banks) conflict pattern in the score dot-products.

#define NNODE 64
#define S 132   // padded feature-row stride (floats); 132*4=528 bytes, 16B aligned

template <int V> struct ic { static constexpr int v = V; };

__global__ __launch_bounds__(256, 4)
void sag_kernel(const int* __restrict__ aa, const float* __restrict__ pos,
                const float* __restrict__ cdr,
                const float* __restrict__ emb,
                const float* __restrict__ W1, const float* __restrict__ b1,
                const float* __restrict__ p1wl, const float* __restrict__ p1bl, const float* __restrict__ p1wr,
                const float* __restrict__ W2, const float* __restrict__ b2,
                const float* __restrict__ p2wl, const float* __restrict__ p2bl, const float* __restrict__ p2wr,
                const float* __restrict__ W3, const float* __restrict__ b3,
                const float* __restrict__ p3wl, const float* __restrict__ p3bl, const float* __restrict__ p3wr,
                const float* __restrict__ mW1, const float* __restrict__ mb1,
                const float* __restrict__ mW2, const float* __restrict__ mb2,
                const float* __restrict__ mW3, const float* __restrict__ mb3,
                float* __restrict__ out)
{
    __shared__ __align__(16) float sA[64 * S];     // 33 KB main feature buffer (padded rows)
    __shared__ __align__(16) float sX0[64 * 36];   // 9 KB padded input features
    __shared__ float sU[64], sV[64], sScore[64], sVals[64], sDinv[64];
    __shared__ int   sIdx[64], sG[64], sNcnt[64], sNbr[64 * 4];
    __shared__ float sR[256], sH[128], sH2[64], sRed[64];

    const int b   = blockIdx.x;
    const int tid = threadIdx.x;
    const int c   = tid & 127;   // output column (feature)
    const int rh  = tid >> 7;    // row half (0/1)

    // ---------------- build x0 = [emb[aa], pos, is_cdr3] padded to 36 ----------------
    for (int e = tid; e < 64 * 36; e += 256) {
        int i = e / 36, f = e - i * 36;
        float v = 0.f;
        if (f < 32)       v = __ldg(&emb[aa[b * 64 + i] * 32 + f]);
        else if (f == 32) v = __ldg(&pos[b * 64 + i]);
        else if (f == 33) v = __ldg(&cdr[b * 64 + i]);
        sX0[e] = v;
    }
    if (tid < 64) sG[tid] = tid;   // original indices (identity at stage 1)
    __syncthreads();

    // ---------------- helpers (compile-time n for full unroll / no local spill) -----

    // neighbor lists + dinv from tracked original indices (band |gi-gj|<=2)
    auto build_graph = [&](auto NC) {
        constexpr int n = decltype(NC)::v;
        if (tid < n) {
            int gi = sG[tid];
            int cnt = 0;
            #pragma unroll 4
            for (int q = 0; q < n; q++) {
                if (q == tid) continue;
                int d = gi - sG[q]; d = d < 0 ? -d : d;
                if (d <= 2) sNbr[tid * 4 + (cnt++)] = q;
            }
            sNcnt[tid] = cnt;
            sDinv[tid] = rsqrtf((float)(cnt + 1));
        }
        __syncthreads();
    };

    // y = relu( dinv_i * sum_{j in nbr(i) U {i}} dinv_j * src[j] + bias ); src may alias dst
    auto gcn_agg = [&](auto NC, const float* src, float* dst, const float* bias) {
        constexpr int n = decltype(NC)::v;
        constexpr int m = n / 2;
        float tmp[m];
        float bc = __ldg(&bias[c]);
        #pragma unroll
        for (int t = 0; t < m; t++) {
            int p = rh * m + t;
            float acc = sDinv[p] * src[p * S + c];
            int cnt = sNcnt[p];
            for (int tt = 0; tt < cnt; tt++) {
                int q = sNbr[p * 4 + tt];
                acc += sDinv[q] * src[q * S + c];
            }
            tmp[t] = fmaxf(sDinv[p] * acc + bc, 0.f);
        }
        __syncthreads();
        #pragma unroll
        for (int t = 0; t < m; t++) dst[(rh * m + t) * S + c] = tmp[t];
        __syncthreads();
    };

    // SAGPool GraphConv scores: s_i = sum_{j in nbr(i)} (x_j . wl) + bl + x_i . wr
    auto scores = [&](auto NC, const float* src, const float* wl, const float* wr, const float* blp) {
        constexpr int n = decltype(NC)::v;
        if (tid < 4 * n) {
            int i = tid >> 2, sl = tid & 3;
            float u = 0.f, v = 0.f;
            #pragma unroll 8
            for (int c0 = 0; c0 < 32; c0++) {
                float xf = src[i * S + sl * 32 + c0];   // padded stride: 4-way max conflict
                u += xf * __ldg(&wl[sl * 32 + c0]);
                v += xf * __ldg(&wr[sl * 32 + c0]);
            }
            u += __shfl_xor_sync(0xffffffffu, u, 1);
            u += __shfl_xor_sync(0xffffffffu, u, 2);
            v += __shfl_xor_sync(0xffffffffu, v, 1);
            v += __shfl_xor_sync(0xffffffffu, v, 2);
            if (sl == 0) { sU[i] = u; sV[i] = v; }
        }
        __syncthreads();
        if (tid < n) {
            float s = __ldg(blp) + sV[tid];
            int cnt = sNcnt[tid];
            for (int t = 0; t < cnt; t++) s += sU[sNbr[tid * 4 + t]];
            sScore[tid] = s;
        }
        __syncthreads();
    };

    // stable descending top-k by ranking (matches jax.lax.top_k tie semantics),
    // then remap original-index array and pre-tanh the gate values
    auto topk = [&](auto NC, auto KC) {
        constexpr int n = decltype(NC)::v;
        constexpr int k = decltype(KC)::v;
        if (tid < n) {
            float my = sScore[tid];
            int rank = 0;
            #pragma unroll 8
            for (int j = 0; j < n; j++) {
                float sj = sScore[j];
                rank += (sj > my) || (sj == my && j < tid);
            }
            if (rank < k) { sIdx[rank] = tid; sVals[rank] = my; }
        }
        __syncthreads();
        int ng = 0;
        if (tid < k) ng = sG[sIdx[tid]];
        __syncthreads();
        if (tid < k) { sG[tid] = ng; sVals[tid] = tanhf(sVals[tid]); }
        __syncthreads();
    };

    // xs[p] = src[idx[p]] * tanh(vals[p]); src/dst may alias (register staging)
    auto gather = [&](auto KC, const float* src, float* dst) {
        constexpr int k = decltype(KC)::v;
        constexpr int m = (k * 128) / 256;
        float tmp[m];
        #pragma unroll
        for (int t = 0; t < m; t++) {
            int e = tid + t * 256;
            int p = e >> 7, cc = e & 127;
            tmp[t] = src[sIdx[p] * S + cc] * sVals[p];
        }
        __syncthreads();
        #pragma unroll
        for (int t = 0; t < m; t++) {
            int e = tid + t * 256;
            dst[(e >> 7) * S + (e & 127)] = tmp[t];
        }
        __syncthreads();
    };

    // r += [max over nodes, mean over nodes]
    auto readout = [&](auto KC, const float* src, bool first) {
        constexpr int k = decltype(KC)::v;
        if (tid < 128) {
            float mx = src[tid], sm = src[tid];
            #pragma unroll
            for (int p = 1; p < k; p++) {
                float xv = src[p * S + tid];
                mx = fmaxf(mx, xv);
                sm += xv;
            }
            float mean = sm * (1.f / (float)k);
            if (first) { sR[tid] = mx; sR[128 + tid] = mean; }
            else       { sR[tid] += mx; sR[128 + tid] += mean; }
        }
        __syncthreads();
    };

    // dst[p][c] = sum_k src[p][k] * W[k][c], n rows, K=128.
    // x rows broadcast via float4 LDS (no conflicts); W via coalesced LDG (L1/L2-resident).
    auto mm128 = [&](auto NC, const float* src, float* dst, const float* W) {
        constexpr int n = decltype(NC)::v;
        constexpr int m = n / 2;
        float acc[m];
        #pragma unroll
        for (int t = 0; t < m; t++) acc[t] = 0.f;
        #pragma unroll 4
        for (int kq = 0; kq < 32; kq++) {
            float w0 = __ldg(&W[(4 * kq + 0) * 128 + c]);
            float w1 = __ldg(&W[(4 * kq + 1) * 128 + c]);
            float w2 = __ldg(&W[(4 * kq + 2) * 128 + c]);
            float w3 = __ldg(&W[(4 * kq + 3) * 128 + c]);
            #pragma unroll
            for (int t = 0; t < m; t++) {
                float4 x = *(const float4*)&src[(rh * m + t) * S + 4 * kq];
                acc[t] += x.x * w0 + x.y * w1 + x.z * w2 + x.w * w3;
            }
        }
        #pragma unroll
        for (int t = 0; t < m; t++) dst[(rh * m + t) * S + c] = acc[t];
        __syncthreads();
    };

    // ---------------- stage 1: GCN1 matmul (64 nodes, input 34-d) ----------------
    // Two 16-row passes per thread-half to cap live registers at ~16 accumulators
    // (keeps us under the 64-reg budget of __launch_bounds__(256,4); no spills).
    #pragma unroll 1
    for (int ch = 0; ch < 2; ch++) {
        float acc[16];
        #pragma unroll
        for (int t = 0; t < 16; t++) acc[t] = 0.f;
        #pragma unroll 2
        for (int kq = 0; kq < 8; kq++) {
            float w0 = __ldg(&W1[(4 * kq + 0) * 128 + c]);
            float w1 = __ldg(&W1[(4 * kq + 1) * 128 + c]);
            float w2 = __ldg(&W1[(4 * kq + 2) * 128 + c]);
            float w3 = __ldg(&W1[(4 * kq + 3) * 128 + c]);
            #pragma unroll
            for (int t = 0; t < 16; t++) {
                int r = rh * 32 + ch * 16 + t;
                float4 x = *(const float4*)&sX0[r * 36 + 4 * kq];
                acc[t] += x.x * w0 + x.y * w1 + x.z * w2 + x.w * w3;
            }
        }
        { // remainder k = 32, 33
            float w0 = __ldg(&W1[32 * 128 + c]);
            float w1 = __ldg(&W1[33 * 128 + c]);
            #pragma unroll
            for (int t = 0; t < 16; t++) {
                int r = rh * 32 + ch * 16 + t;
                acc[t] += sX0[r * 36 + 32] * w0 + sX0[r * 36 + 33] * w1;
            }
        }
        #pragma unroll
        for (int t = 0; t < 16; t++) sA[(rh * 32 + ch * 16 + t) * S + c] = acc[t];
    }
    __syncthreads();

    build_graph(ic<64>{});
    gcn_agg(ic<64>{}, sA, sA, b1);
    scores(ic<64>{}, sA, p1wl, p1wr, p1bl);
    topk(ic<64>{}, ic<32>{});
    gather(ic<32>{}, sA, sA);          // x1 pooled -> rows 0..31
    readout(ic<32>{}, sA, true);

    // ---------------- stage 2: GCN2 (32 nodes) ----------------
    build_graph(ic<32>{});
    mm128(ic<32>{}, sA, sA + 32 * S, W2);       // xw -> rows 32..63
    gcn_agg(ic<32>{}, sA + 32 * S, sA, b2);     // x2 -> rows 0..31
    scores(ic<32>{}, sA, p2wl, p2wr, p2bl);
    topk(ic<32>{}, ic<16>{});
    gather(ic<16>{}, sA, sA);          // x2 pooled -> rows 0..15
    readout(ic<16>{}, sA, false);

    // ---------------- stage 3: GCN3 (16 nodes) ----------------
    build_graph(ic<16>{});
    mm128(ic<16>{}, sA, sA + 32 * S, W3);       // xw -> rows 32..47
    gcn_agg(ic<16>{}, sA + 32 * S, sA, b3);     // x3 -> rows 0..15
    scores(ic<16>{}, sA, p3wl, p3wr, p3bl);
    topk(ic<16>{}, ic<8>{});
    gather(ic<8>{}, sA, sA);           // x3 pooled -> rows 0..7
    readout(ic<8>{}, sA, false);

    // ---------------- MLP head: 256 -> 128 -> 64 -> 1 ----------------
    if (tid < 128) {
        float a = __ldg(&mb1[tid]);
        #pragma unroll 8
        for (int k = 0; k < 256; k++) a += sR[k] * __ldg(&mW1[k * 128 + tid]);
        sH[tid] = fmaxf(a, 0.f);
    }
    __syncthreads();
    if (tid < 64) {
        float a = __ldg(&mb2[tid]);
        #pragma unroll 8
        for (int k = 0; k < 128; k++) a += sH[k] * __ldg(&mW2[k * 64 + tid]);
        sH2[tid] = fmaxf(a, 0.f);
    }
    __syncthreads();
    if (tid < 64) sRed[tid] = sH2[tid] * __ldg(&mW3[tid]);
    __syncthreads();
    if (tid < 32) {
        float v = sRed[tid] + sRed[tid + 32];
        #pragma unroll
        for (int o = 16; o; o >>= 1) v += __shfl_xor_sync(0xffffffffu, v, o);
        if (tid == 0) out[b] = v + __ldg(&mb3[0]);
    }
}

extern "C" void kernel_launch(void* const* d_in, const int* in_sizes, int n_in,
                              void* d_out, int out_size)
{
    (void)n_in; (void)out_size;
    int B = in_sizes[0] / NNODE;   // 4096
    sag_kernel<<<B, 256>>>(
        (const int*)  d_in[0],   // aa
        (const float*)d_in[1],   // pos
        (const float*)d_in[2],   // is_cdr3
        // d_in[3] = adj  (band matrix; derived analytically, never read)
        (const float*)d_in[4],   // emb
        (const float*)d_in[5],  (const float*)d_in[6],                       // W1, b1
        (const float*)d_in[7],  (const float*)d_in[8],  (const float*)d_in[9],   // p1 wl/bl/wr
        (const float*)d_in[10], (const float*)d_in[11],                      // W2, b2
        (const float*)d_in[12], (const float*)d_in[13], (const float*)d_in[14],  // p2
        (const float*)d_in[15], (const float*)d_in[16],                      // W3, b3
        (const float*)d_in[17], (const float*)d_in[18], (const float*)d_in[19],  // p3
        (const float*)d_in[20], (const float*)d_in[21],                      // mW1, mb1
        (const float*)d_in[22], (const float*)d_in[23],                      // mW2, mb2
        (const float*)d_in[24], (const float*)d_in[25],                      // mW3, mb3
        (float*)d_out);
}

// round 3
// speedup vs baseline: 1.2526x; 1.2526x over previous
#include <cuda_runtime.h>

// SagPoolBindingNet: B=4096 graphs, N=64 nodes, band adjacency (|i-j|<=2).
// One CTA per graph; band structure derived analytically (64MB adj never read).
// R3: float4 retile (4 cols/thread) everywhere to cut LSU instruction count
// ~2.5x — R2 ncu showed l1tex pipe 64% (binding) vs fma 24%.

#define NNODE 64
#define S 132   // padded feature-row stride (floats); breaks stride-128 bank pattern

template <int V> struct ic { static constexpr int v = V; };

__device__ __forceinline__ float4 f4_fma4(float4 acc, const float4 x,
                                          const float4 w0, const float4 w1,
                                          const float4 w2, const float4 w3) {
    acc.x += x.x*w0.x + x.y*w1.x + x.z*w2.x + x.w*w3.x;
    acc.y += x.x*w0.y + x.y*w1.y + x.z*w2.y + x.w*w3.y;
    acc.z += x.x*w0.z + x.y*w1.z + x.z*w2.z + x.w*w3.z;
    acc.w += x.x*w0.w + x.y*w1.w + x.z*w2.w + x.w*w3.w;
    return acc;
}
__device__ __forceinline__ float4 f4_axpy(float4 acc, float s, const float4 v) {
    acc.x += s*v.x; acc.y += s*v.y; acc.z += s*v.z; acc.w += s*v.w; return acc;
}
__device__ __forceinline__ float4 f4_scale(float s, const float4 v) {
    return make_float4(s*v.x, s*v.y, s*v.z, s*v.w);
}
__device__ __forceinline__ float4 f4_relu_sab(float s, float4 a, float4 b) { // relu(s*a+b)
    return make_float4(fmaxf(s*a.x+b.x,0.f), fmaxf(s*a.y+b.y,0.f),
                       fmaxf(s*a.z+b.z,0.f), fmaxf(s*a.w+b.w,0.f));
}
__device__ __forceinline__ float4 f4_max(float4 a, float4 b) {
    return make_float4(fmaxf(a.x,b.x), fmaxf(a.y,b.y), fmaxf(a.z,b.z), fmaxf(a.w,b.w));
}
__device__ __forceinline__ float4 f4_add(float4 a, float4 b) {
    return make_float4(a.x+b.x, a.y+b.y, a.z+b.z, a.w+b.w);
}

__global__ __launch_bounds__(256, 4)
void sag_kernel(const int* __restrict__ aa, const float* __restrict__ pos,
                const float* __restrict__ cdr,
                const float* __restrict__ emb,
                const float* __restrict__ W1, const float* __restrict__ b1,
                const float* __restrict__ p1wl, const float* __restrict__ p1bl, const float* __restrict__ p1wr,
                const float* __restrict__ W2, const float* __restrict__ b2,
                const float* __restrict__ p2wl, const float* __restrict__ p2bl, const float* __restrict__ p2wr,
                const float* __restrict__ W3, const float* __restrict__ b3,
                const float* __restrict__ p3wl, const float* __restrict__ p3bl, const float* __restrict__ p3wr,
                const float* __restrict__ mW1, const float* __restrict__ mb1,
                const float* __restrict__ mW2, const float* __restrict__ mb2,
                const float* __restrict__ mW3, const float* __restrict__ mb3,
                float* __restrict__ out)
{
    __shared__ __align__(16) float sA[64 * S];     // 33 KB feature buffer (padded rows)
    __shared__ __align__(16) float sX0[64 * 36];   // 9 KB input feats; reused as sP in MLP
    __shared__ __align__(16) float sR[256];
    __shared__ __align__(16) float sH[128];
    __shared__ float sU[64], sV[64], sScore[64], sVals[64], sDinv[64], sH2[64];
    __shared__ int   sIdx[64], sG[64], sNcnt[64], sNbr[64 * 4];
    float* const sP = sX0;   // MLP split-K partials (sX0 dead by then)

    const int b   = blockIdx.x;
    const int tid = threadIdx.x;
    const int cg  = tid & 31;   // column group: cols 4cg..4cg+3
    const int rg  = tid >> 5;   // row group (0..7)

    // ---------------- build x0 = [emb[aa], pos, is_cdr3] padded to 36 ----------------
    for (int e = tid; e < 64 * 36; e += 256) {
        int i = e / 36, f = e - i * 36;
        float v = 0.f;
        if (f < 32)       v = __ldg(&emb[aa[b * 64 + i] * 32 + f]);
        else if (f == 32) v = __ldg(&pos[b * 64 + i]);
        else if (f == 33) v = __ldg(&cdr[b * 64 + i]);
        sX0[e] = v;
    }
    if (tid < 64) sG[tid] = tid;   // original indices (identity at stage 1)
    __syncthreads();

    // ---------------- helpers ----------------

    // neighbor lists + dinv from tracked original indices (band |gi-gj|<=2)
    auto build_graph = [&](auto NC) {
        constexpr int n = decltype(NC)::v;
        if (tid < n) {
            int gi = sG[tid];
            int cnt = 0;
            #pragma unroll 4
            for (int q = 0; q < n; q++) {
                if (q == tid) continue;
                int d = gi - sG[q]; d = d < 0 ? -d : d;
                if (d <= 2) sNbr[tid * 4 + (cnt++)] = q;
            }
            sNcnt[tid] = cnt;
            sDinv[tid] = rsqrtf((float)(cnt + 1));
        }
        __syncthreads();
    };

    // y = relu( dinv_i * sum_{j in nbr(i) U {i}} dinv_j * src[j] + bias ); src may alias dst
    auto gcn_agg = [&](auto NC, const float* src, float* dst, const float* bias) {
        constexpr int n = decltype(NC)::v;
        constexpr int m = n / 8;   // rows per thread
        const float4 bc = __ldg(reinterpret_cast<const float4*>(bias) + cg);
        float4 tmp[m];
        #pragma unroll
        for (int t = 0; t < m; t++) {
            const int p = rg * m + t;
            const float dp = sDinv[p];
            float4 acc = f4_scale(dp, *(const float4*)&src[p * S + 4 * cg]);
            const int cnt = sNcnt[p];
            for (int tt = 0; tt < cnt; tt++) {
                const int q = sNbr[p * 4 + tt];
                acc = f4_axpy(acc, sDinv[q], *(const float4*)&src[q * S + 4 * cg]);
            }
            tmp[t] = f4_relu_sab(dp, acc, bc);
        }
        __syncthreads();
        #pragma unroll
        for (int t = 0; t < m; t++) *(float4*)&dst[(rg * m + t) * S + 4 * cg] = tmp[t];
        __syncthreads();
    };

    // SAGPool GraphConv scores: s_i = sum_{j in nbr(i)} (x_j . wl) + bl + x_i . wr
    auto scores = [&](auto NC, const float* src, const float* wl, const float* wr, const float* blp) {
        constexpr int n = decltype(NC)::v;
        if (tid < 4 * n) {
            const int i = tid >> 2, sl = tid & 3;
            float u = 0.f, v = 0.f;
            #pragma unroll
            for (int c4 = 0; c4 < 8; c4++) {
                const float4 xf = *(const float4*)&src[i * S + sl * 32 + 4 * c4];
                const float4 a  = __ldg(reinterpret_cast<const float4*>(wl + sl * 32) + c4);
                const float4 bb = __ldg(reinterpret_cast<const float4*>(wr + sl * 32) + c4);
                u += xf.x*a.x + xf.y*a.y + xf.z*a.z + xf.w*a.w;
                v += xf.x*bb.x + xf.y*bb.y + xf.z*bb.z + xf.w*bb.w;
            }
            u += __shfl_xor_sync(0xffffffffu, u, 1);
            u += __shfl_xor_sync(0xffffffffu, u, 2);
            v += __shfl_xor_sync(0xffffffffu, v, 1);
            v += __shfl_xor_sync(0xffffffffu, v, 2);
            if (sl == 0) { sU[i] = u; sV[i] = v; }
        }
        __syncthreads();
        if (tid < n) {
            float s = __ldg(blp) + sV[tid];
            const int cnt = sNcnt[tid];
            for (int t = 0; t < cnt; t++) s += sU[sNbr[tid * 4 + t]];
            sScore[tid] = s;
        }
        __syncthreads();
    };

    // stable descending top-k by ranking (matches jax.lax.top_k tie semantics)
    auto topk = [&](auto NC, auto KC) {
        constexpr int n = decltype(NC)::v;
        constexpr int k = decltype(KC)::v;
        if (tid < n) {
            const float my = sScore[tid];
            int rank = 0;
            #pragma unroll 8
            for (int j = 0; j < n; j++) {
                const float sj = sScore[j];
                rank += (sj > my) || (sj == my && j < tid);
            }
            if (rank < k) { sIdx[rank] = tid; sVals[rank] = my; }
        }
        __syncthreads();
        int ng = 0;
        if (tid < k) ng = sG[sIdx[tid]];
        __syncthreads();
        if (tid < k) { sG[tid] = ng; sVals[tid] = tanhf(sVals[tid]); }
        __syncthreads();
    };

    // xs[p] = src[idx[p]] * tanh(vals[p]); src/dst may alias (register staging)
    auto gather = [&](auto KC, const float* src, float* dst) {
        constexpr int k  = decltype(KC)::v;
        constexpr int m4 = (k * 32) / 256;   // float4 groups per thread
        float4 tmp[m4];
        #pragma unroll
        for (int t = 0; t < m4; t++) {
            const int e = tid + t * 256;
            const int p = e >> 5, g4 = e & 31;
            tmp[t] = f4_scale(sVals[p], *(const float4*)&src[sIdx[p] * S + 4 * g4]);
        }
        __syncthreads();
        #pragma unroll
        for (int t = 0; t < m4; t++) {
            const int e = tid + t * 256;
            *(float4*)&dst[(e >> 5) * S + 4 * (e & 31)] = tmp[t];
        }
        __syncthreads();
    };

    // r += [global_max, global_mean] over k node rows
    auto readout = [&](auto KC, const float* src, bool first) {
        constexpr int k = decltype(KC)::v;
        if (tid < 32) {
            float4 mx = *(const float4*)&src[4 * tid];
            float4 sm = mx;
            #pragma unroll
            for (int p = 1; p < k; p++) {
                const float4 xv = *(const float4*)&src[p * S + 4 * tid];
                mx = f4_max(mx, xv);
                sm = f4_add(sm, xv);
            }
            const float4 mean = f4_scale(1.f / (float)k, sm);
            if (first) {
                *(float4*)&sR[4 * tid]       = mx;
                *(float4*)&sR[128 + 4 * tid] = mean;
            } else {
                *(float4*)&sR[4 * tid]       = f4_add(*(const float4*)&sR[4 * tid], mx);
                *(float4*)&sR[128 + 4 * tid] = f4_add(*(const float4*)&sR[128 + 4 * tid], mean);
            }
        }
        __syncthreads();
    };

    // dst[p][c] = sum_k src[p][k] * W[k][c]; n rows, K=128. 4 cols x m rows per thread.
    auto mm128 = [&](auto NC, const float* src, float* dst, const float* W) {
        constexpr int n = decltype(NC)::v;
        constexpr int m = n / 8;
        float4 acc[m];
        #pragma unroll
        for (int t = 0; t < m; t++) acc[t] = make_float4(0.f, 0.f, 0.f, 0.f);
        #pragma unroll 2
        for (int kc = 0; kc < 128; kc += 4) {
            const float4 w0 = __ldg(reinterpret_cast<const float4*>(W + (kc + 0) * 128) + cg);
            const float4 w1 = __ldg(reinterpret_cast<const float4*>(W + (kc + 1) * 128) + cg);
            const float4 w2 = __ldg(reinterpret_cast<const float4*>(W + (kc + 2) * 128) + cg);
            const float4 w3 = __ldg(reinterpret_cast<const float4*>(W + (kc + 3) * 128) + cg);
            #pragma unroll
            for (int t = 0; t < m; t++) {
                const float4 x = *(const float4*)&src[(rg * m + t) * S + kc];
                acc[t] = f4_fma4(acc[t], x, w0, w1, w2, w3);
            }
        }
        #pragma unroll
        for (int t = 0; t < m; t++) *(float4*)&dst[(rg * m + t) * S + 4 * cg] = acc[t];
        __syncthreads();
    };

    // ---------------- stage 1: GCN1 matmul (64 rows, K=34) ----------------
    // 8 rows/thread in two 4-row passes (caps live registers; no spills @64-reg budget)
    #pragma unroll 1
    for (int ch = 0; ch < 2; ch++) {
        float4 acc[4];
        #pragma unroll
        for (int t = 0; t < 4; t++) acc[t] = make_float4(0.f, 0.f, 0.f, 0.f);
        #pragma unroll 2
        for (int kc = 0; kc < 32; kc += 4) {
            const float4 w0 = __ldg(reinterpret_cast<const float4*>(W1 + (kc + 0) * 128) + cg);
            const float4 w1 = __ldg(reinterpret_cast<const float4*>(W1 + (kc + 1) * 128) + cg);
            const float4 w2 = __ldg(reinterpret_cast<const float4*>(W1 + (kc + 2) * 128) + cg);
            const float4 w3 = __ldg(reinterpret_cast<const float4*>(W1 + (kc + 3) * 128) + cg);
            #pragma unroll
            for (int t = 0; t < 4; t++) {
                const int p = rg * 8 + ch * 4 + t;
                const float4 x = *(const float4*)&sX0[p * 36 + kc];
                acc[t] = f4_fma4(acc[t], x, w0, w1, w2, w3);
            }
        }
        { // remainder k = 32, 33
            const float4 wa = __ldg(reinterpret_cast<const float4*>(W1 + 32 * 128) + cg);
            const float4 wb = __ldg(reinterpret_cast<const float4*>(W1 + 33 * 128) + cg);
            #pragma unroll
            for (int t = 0; t < 4; t++) {
                const int p = rg * 8 + ch * 4 + t;
                const float2 x2 = *(const float2*)&sX0[p * 36 + 32];
                acc[t] = f4_axpy(acc[t], x2.x, wa);
                acc[t] = f4_axpy(acc[t], x2.y, wb);
            }
        }
        #pragma unroll
        for (int t = 0; t < 4; t++)
            *(float4*)&sA[(rg * 8 + ch * 4 + t) * S + 4 * cg] = acc[t];
    }
    __syncthreads();

    build_graph(ic<64>{});
    gcn_agg(ic<64>{}, sA, sA, b1);
    scores(ic<64>{}, sA, p1wl, p1wr, p1bl);
    topk(ic<64>{}, ic<32>{});
    gather(ic<32>{}, sA, sA);          // x1 pooled -> rows 0..31
    readout(ic<32>{}, sA, true);

    // ---------------- stage 2: GCN2 (32 nodes) ----------------
    build_graph(ic<32>{});
    mm128(ic<32>{}, sA, sA + 32 * S, W2);       // xw -> rows 32..63
    gcn_agg(ic<32>{}, sA + 32 * S, sA, b2);     // x2 -> rows 0..31
    scores(ic<32>{}, sA, p2wl, p2wr, p2bl);
    topk(ic<32>{}, ic<16>{});
    gather(ic<16>{}, sA, sA);          // x2 pooled -> rows 0..15
    readout(ic<16>{}, sA, false);

    // ---------------- stage 3: GCN3 (16 nodes) ----------------
    build_graph(ic<16>{});
    mm128(ic<16>{}, sA, sA + 32 * S, W3);       // xw -> rows 32..47
    gcn_agg(ic<16>{}, sA + 32 * S, sA, b3);     // x3 -> rows 0..15
    scores(ic<16>{}, sA, p3wl, p3wr, p3bl);
    topk(ic<16>{}, ic<8>{});
    gather(ic<8>{}, sA, sA);           // x3 pooled -> rows 0..7
    readout(ic<8>{}, sA, false);

    // ---------------- MLP head: 256 -> 128 -> 64 -> 1 (split-K over all threads) ----
    {   // layer 1: 256 -> 128
        const int h = tid >> 7, col = tid & 127;
        float a = 0.f;
        #pragma unroll 8
        for (int k = 0; k < 128; k++) a += sR[h * 128 + k] * __ldg(&mW1[(h * 128 + k) * 128 + col]);
        sP[tid] = a;
        __syncthreads();
        if (tid < 128) sH[tid] = fmaxf(sP[tid] + sP[128 + tid] + __ldg(&mb1[tid]), 0.f);
        __syncthreads();
    }
    {   // layer 2: 128 -> 64
        const int h = tid >> 6, col = tid & 63;
        float a = 0.f;
        #pragma unroll 8
        for (int k = 0; k < 32; k++) a += sH[h * 32 + k] * __ldg(&mW2[(h * 32 + k) * 64 + col]);
        sP[tid] = a;
        __syncthreads();
        if (tid < 64)
            sH2[tid] = fmaxf(sP[tid] + sP[64 + tid] + sP[128 + tid] + sP[192 + tid] + __ldg(&mb2[tid]), 0.f);
        __syncthreads();
    }
    if (tid < 64) sP[tid] = sH2[tid] * __ldg(&mW3[tid]);
    __syncthreads();
    if (tid < 32) {
        float v = sP[tid] + sP[tid + 32];
        #pragma unroll
        for (int o = 16; o; o >>= 1) v += __shfl_xor_sync(0xffffffffu, v, o);
        if (tid == 0) out[b] = v + __ldg(&mb3[0]);
    }
}

extern "C" void kernel_launch(void* const* d_in, const int* in_sizes, int n_in,
                              void* d_out, int out_size)
{
    (void)n_in; (void)out_size;
    int B = in_sizes[0] / NNODE;   // 4096
    sag_kernel<<<B, 256>>>(
        (const int*)  d_in[0],   // aa
        (const float*)d_in[1],   // pos
        (const float*)d_in[2],   // is_cdr3
        // d_in[3] = adj  (band matrix; derived analytically, never read)
        (const float*)d_in[4],   // emb
        (const float*)d_in[5],  (const float*)d_in[6],                       // W1, b1
        (const float*)d_in[7],  (const float*)d_in[8],  (const float*)d_in[9],   // p1 wl/bl/wr
        (const float*)d_in[10], (const float*)d_in[11],                      // W2, b2
        (const float*)d_in[12], (const float*)d_in[13], (const float*)d_in[14],  // p2
        (const float*)d_in[15], (const float*)d_in[16],                      // W3, b3
        (const float*)d_in[17], (const float*)d_in[18], (const float*)d_in[19],  // p3
        (const float*)d_in[20], (const float*)d_in[21],                      // mW1, mb1
        (const float*)d_in[22], (const float*)d_in[23],                      // mW2, mb2
        (const float*)d_in[24], (const float*)d_in[25],                      // mW3, mb3
        (float*)d_out);
}